// round 11
// baseline (speedup 1.0000x reference)
#include <cuda_runtime.h>
#include <math.h>
#include <stdint.h>

#define NC 200000
#define NF 64
#define NH 128
#define NS 512

// ---- scratch ----
__device__ float    d_logits[NC];
__device__ float    d_e[NC];
__device__ float    d_w2k[NH];
__device__ uint32_t d_W1frag[NF * NH];  // W1 in tf32, MMA-fragment order
__device__ float    d_c2;
__device__ float    d_sums[NS];
__device__ float    d_sl[NS];
__device__ float    d_cntf[NS];

__device__ __forceinline__ uint32_t f2tf32(float v) {
    uint32_t u;
    asm("cvt.rna.tf32.f32 %0, %1;" : "=r"(u) : "f"(v));
    return u;
}

__device__ __forceinline__ void mma_tf32(float c[4], const uint32_t a[4],
                                         uint32_t b0, uint32_t b1) {
    asm volatile(
        "mma.sync.aligned.m16n8k8.row.col.f32.tf32.tf32.f32 "
        "{%0,%1,%2,%3}, {%4,%5,%6,%7}, {%8,%9}, {%0,%1,%2,%3};"
        : "+f"(c[0]), "+f"(c[1]), "+f"(c[2]), "+f"(c[3])
        : "r"(a[0]), "r"(a[1]), "r"(a[2]), "r"(a[3]), "r"(b0), "r"(b1));
}

// ---- launch 0: prep (W1 frag pack, w2k fold, c2) ----
__global__ void k_prep(const float* __restrict__ W1, const float* __restrict__ W2,
                       const float* __restrict__ b2, const float* __restrict__ kw) {
    int b = blockIdx.x;
    int tid = threadIdx.x;  // 128
    if (b < 16) {
        int j4 = tid >> 5, lane = tid & 31;
        int q = lane & 3, g = lane >> 2;
        int col = b * 8 + g;
        int r0 = 16 * j4 + q;
        uint4 v;
        v.x = f2tf32(W1[(r0 + 0) * NH + col]);
        v.y = f2tf32(W1[(r0 + 4) * NH + col]);
        v.z = f2tf32(W1[(r0 + 8) * NH + col]);
        v.w = f2tf32(W1[(r0 + 12) * NH + col]);
        ((uint4*)d_W1frag)[(b * 4 + j4) * 32 + lane] = v;
    } else if (b < 32) {
        int w = tid >> 5, l = tid & 31;
        int rbase = (b - 16) * 8 + w * 2;
#pragma unroll
        for (int rr = 0; rr < 2; rr++) {
            int h = rbase + rr;
            float s = W2[h * NH + l] * kw[l] + W2[h * NH + l + 32] * kw[l + 32] +
                      W2[h * NH + l + 64] * kw[l + 64] + W2[h * NH + l + 96] * kw[l + 96];
            for (int o = 16; o; o >>= 1) s += __shfl_xor_sync(0xffffffffu, s, o);
            if (l == 0) d_w2k[h] = s;
        }
    } else {
        float c = (tid < NH) ? b2[tid] * kw[tid] : 0.f;
        for (int o = 16; o; o >>= 1) c += __shfl_xor_sync(0xffffffffu, c, o);
        __shared__ float red[4];
        if ((tid & 31) == 0) red[tid >> 5] = c;
        __syncthreads();
        if (tid == 0) d_c2 = red[0] + red[1] + red[2] + red[3];
    }
}

// ================== launch 1: tf32 mma.sync MLP (monolithic) ==================
#define FS 68
#define OFF_FEAT 0
#define OFF_B1   (128 * FS * 4)
#define OFF_WK   (OFF_B1 + 512)
#define SMEM_MLP (OFF_WK + 512)

__global__ void __launch_bounds__(256, 4) k_mlp(const float* __restrict__ feat,
                                                const float* __restrict__ b1) {
    extern __shared__ char smem[];
    float* featS = (float*)(smem + OFF_FEAT);
    float* b1s   = (float*)(smem + OFF_B1);
    float* wks   = (float*)(smem + OFF_WK);

    int tid = threadIdx.x;
    int wid = tid >> 5, lane = tid & 31;
    int g = lane >> 2, q = lane & 3;
    int base = blockIdx.x * 128;

    for (int i = tid; i < 128 * 16; i += 256) {
        int row = i >> 4, f4 = i & 15;
        float4 v = make_float4(0.f, 0.f, 0.f, 0.f);
        int c = base + row;
        if (c < NC) v = *(const float4*)(feat + (size_t)c * NF + f4 * 4);
        *(float4*)(featS + row * FS + f4 * 4) = v;
    }
    if (tid < NH) { b1s[tid] = b1[tid]; wks[tid] = d_w2k[tid]; }
    __syncthreads();

    uint32_t a[8][4];
    int r0 = wid * 16 + g;
#pragma unroll
    for (int kt = 0; kt < 8; kt++) {
        int k0 = kt * 8;
        a[kt][0] = f2tf32(featS[r0 * FS + k0 + q]);
        a[kt][1] = f2tf32(featS[(r0 + 8) * FS + k0 + q]);
        a[kt][2] = f2tf32(featS[r0 * FS + k0 + q + 4]);
        a[kt][3] = f2tf32(featS[(r0 + 8) * FS + k0 + q + 4]);
    }

    const uint4* fragp = (const uint4*)d_W1frag + lane;
    float acc0 = 0.f, acc1 = 0.f;
#pragma unroll
    for (int nt = 0; nt < 16; nt++) {
        const uint4* fb = fragp + nt * 128;
        uint4 B0 = fb[0];
        uint4 B1 = fb[32];
        uint4 B2 = fb[64];
        uint4 B3 = fb[96];
        float c0[4] = {0.f, 0.f, 0.f, 0.f};
        mma_tf32(c0, a[0], B0.x, B0.y);
        mma_tf32(c0, a[1], B0.z, B0.w);
        mma_tf32(c0, a[2], B1.x, B1.y);
        mma_tf32(c0, a[3], B1.z, B1.w);
        mma_tf32(c0, a[4], B2.x, B2.y);
        mma_tf32(c0, a[5], B2.z, B2.w);
        mma_tf32(c0, a[6], B3.x, B3.y);
        mma_tf32(c0, a[7], B3.z, B3.w);
        int col0 = nt * 8 + 2 * q, col1 = col0 + 1;
        float bb0 = b1s[col0], bb1 = b1s[col1];
        float wk0 = wks[col0], wk1 = wks[col1];
        acc0 += fmaxf(c0[0] + bb0, 0.f) * wk0 + fmaxf(c0[1] + bb1, 0.f) * wk1;
        acc1 += fmaxf(c0[2] + bb0, 0.f) * wk0 + fmaxf(c0[3] + bb1, 0.f) * wk1;
    }

    float c2v = d_c2;
#pragma unroll
    for (int rh = 0; rh < 2; rh++) {
        float v = (rh == 0) ? acc0 : acc1;
        v += __shfl_xor_sync(0xffffffffu, v, 1);
        v += __shfl_xor_sync(0xffffffffu, v, 2);
        v += c2v;
        int c = base + wid * 16 + rh * 8 + g;
        if (c < NC && q == 0) d_logits[c] = v;
    }
}

// ---- launch 2: e[] = exp(logits - logits[0]); init accumulators ----
__global__ void k_einit() {
    int b = blockIdx.x;  // 99 blocks x 256
    int tid = threadIdx.x;
    if (b < 98) {
        float shift = d_logits[0];
        int base = b * 2048;
#pragma unroll
        for (int r = 0; r < 8; r++) {
            int n = base + r * 256 + tid;
            if (n < NC) d_e[n] = expf(d_logits[n] - shift);
        }
    } else {
        d_sums[tid] = 0.f;         d_sums[tid + 256] = 0.f;
        d_sl[tid] = 0.f;           d_sl[tid + 256] = 0.f;
        d_cntf[tid] = 0.f;         d_cntf[tid + 256] = 0.f;
    }
}

// ---- launch 3: fused denom + sparse numerator, warp-per-step ----
// grid (98, 16): 32 steps per block-y -> 1568 CTAs (occupancy not grid-capped).
// smem: es chunk + compacted proof list (idx, logit); hot loop stays slim.
#define CHUNK 2048
#define DTPB 256
#define PMAX 160
__global__ void __launch_bounds__(DTPB) k_denom(const int* __restrict__ sel,
                                                const int* __restrict__ proof) {
    __shared__ float es[CHUNK];
    __shared__ int   spidx[PMAX];
    __shared__ float spval[PMAX];
    __shared__ int   spcnt;
    int tid = threadIdx.x;
    int w = tid >> 5, l = tid & 31;
    int base = blockIdx.x * CHUNK;
    if (tid == 0) spcnt = 0;
    __syncthreads();

    for (int i = tid; i < CHUNK; i += DTPB) {
        int n = base + i;
        float e = 0.f;
        if (n < NC) {
            e = d_e[n];
            if (proof[n]) {
                int p = atomicAdd(&spcnt, 1);
                if (p < PMAX) { spidx[p] = i; spval[p] = d_logits[n]; }
            }
        }
        es[i] = e;
    }
    __syncthreads();
    int P = spcnt;
    if (P > PMAX) P = PMAX;

    bool fast = (base + CHUNK) <= NC;
    for (int si = 0; si < 4; si++) {
        int s = blockIdx.y * 32 + si * 8 + w;
        const int* mrow = sel + (size_t)s * NC + base;
        float ad = 0.f;
        if (fast) {
            const int4* m4 = (const int4*)mrow;
#pragma unroll
            for (int j = 0; j < 16; j++) {
                int p = j * 32 + l;
                int4 m = m4[p];
                float4 e4 = *(const float4*)&es[p * 4];
                if (m.x) ad += e4.x;
                if (m.y) ad += e4.y;
                if (m.z) ad += e4.z;
                if (m.w) ad += e4.w;
            }
        } else {
            for (int j = 0; j < 16; j++) {
                int e0 = j * 128 + l * 4;
#pragma unroll
                for (int p = 0; p < 4; p++) {
                    int n = base + e0 + p;
                    if (n < NC && mrow[e0 + p]) ad += es[e0 + p];
                }
            }
        }
        // sparse numerator gather (rows just streamed -> L1 hits)
        float an = 0.f, ac = 0.f;
        for (int j = l; j < P; j += 32) {
            if (mrow[spidx[j]]) { an += spval[j]; ac += 1.f; }
        }
        for (int o = 16; o; o >>= 1) {
            ad += __shfl_xor_sync(0xffffffffu, ad, o);
            an += __shfl_xor_sync(0xffffffffu, an, o);
            ac += __shfl_xor_sync(0xffffffffu, ac, o);
        }
        if (l == 0) {
            atomicAdd(&d_sums[s], ad);
            atomicAdd(&d_sl[s], an);
            atomicAdd(&d_cntf[s], ac);
        }
    }
}

// ---- launch 4: final loss ----
__global__ void k_final(float* out) {
    float shift = d_logits[0];
    int t = threadIdx.x;  // 512
    float v = (shift + logf(d_sums[t])) - d_sl[t] / d_cntf[t];
    for (int o = 16; o; o >>= 1) v += __shfl_xor_sync(0xffffffffu, v, o);
    __shared__ float red[16];
    if ((t & 31) == 0) red[t >> 5] = v;
    __syncthreads();
    if (t == 0) {
        float tot = 0.f;
#pragma unroll
        for (int w = 0; w < 16; w++) tot += red[w];
        out[0] = tot / (float)NS;
    }
}

extern "C" void kernel_launch(void* const* d_in, const int* in_sizes, int n_in,
                              void* d_out, int out_size) {
    const float* feat = (const float*)d_in[0];
    const float* W1   = (const float*)d_in[1];
    const float* b1   = (const float*)d_in[2];
    const float* W2   = (const float*)d_in[3];
    const float* b2   = (const float*)d_in[4];
    const float* kw   = (const float*)d_in[5];
    const int*   sel  = (const int*)d_in[6];
    const int*   proof= (const int*)d_in[7];
    float* out = (float*)d_out;

    static int smem_set = 0;
    if (!smem_set) {
        cudaFuncSetAttribute(k_mlp, cudaFuncAttributeMaxDynamicSharedMemorySize, SMEM_MLP);
        smem_set = 1;
    }

    k_prep<<<33, 128>>>(W1, W2, b2, kw);                   // 0
    k_mlp<<<(NC + 127) / 128, 256, SMEM_MLP>>>(feat, b1);  // 1
    k_einit<<<99, 256>>>();                                // 2
    dim3 dg(98, 16);
    k_denom<<<dg, DTPB>>>(sel, proof);                     // 3 <- ncu capture slot
    k_final<<<1, NS>>>(out);                               // 4
}

// round 13
// speedup vs baseline: 1.2103x; 1.2103x over previous
#include <cuda_runtime.h>
#include <cuda_fp16.h>
#include <math.h>
#include <stdint.h>

#define NC 200000
#define NF 64
#define NH 128
#define NS 512

// ---- scratch ----
__device__ float    d_logits[NC];
__device__ float    d_w2k[NH];
__device__ uint32_t d_W1frag[NF * NH / 2];  // W1 as f16x2, MMA-fragment order (16 KB)
__device__ float    d_c2;
__device__ float    d_sums[NS];
__device__ float    d_sl[NS];
__device__ float    d_cntf[NS];

__device__ __forceinline__ uint32_t packh2(float a, float b) {
    __half2 h = __floats2half2_rn(a, b);
    return *(uint32_t*)&h;
}

__device__ __forceinline__ void mma_f16(float c[4], const uint32_t a[4],
                                        uint32_t b0, uint32_t b1) {
    asm volatile(
        "mma.sync.aligned.m16n8k16.row.col.f32.f16.f16.f32 "
        "{%0,%1,%2,%3}, {%4,%5,%6,%7}, {%8,%9}, {%0,%1,%2,%3};"
        : "+f"(c[0]), "+f"(c[1]), "+f"(c[2]), "+f"(c[3])
        : "r"(a[0]), "r"(a[1]), "r"(a[2]), "r"(a[3]), "r"(b0), "r"(b1));
}

// ---- launch 0: prep (W1 f16 frag pack, w2k fold, accum init, c2) ----
// blocks 0..15: pack B fragments for n-tile nt=b (threads 0..63 active)
// blocks 16..31: w2k rows; blocks 32..35: accumulator init; block 36: c2
__global__ void k_prep(const float* __restrict__ W1, const float* __restrict__ W2,
                       const float* __restrict__ b2, const float* __restrict__ kw) {
    int b = blockIdx.x;
    int tid = threadIdx.x;  // 128
    if (b < 16) {
        if (tid < 64) {
            int h = tid >> 5, lane = tid & 31;
            int q = lane & 3, g = lane >> 2;
            int col = b * 8 + g;
            // kt pair (2h, 2h+1); kb = kt*16
            int k0 = 32 * h;
            uint4 v;
            v.x = packh2(W1[(k0 + 2 * q) * NH + col],      W1[(k0 + 2 * q + 1) * NH + col]);
            v.y = packh2(W1[(k0 + 2 * q + 8) * NH + col],  W1[(k0 + 2 * q + 9) * NH + col]);
            v.z = packh2(W1[(k0 + 16 + 2 * q) * NH + col], W1[(k0 + 17 + 2 * q) * NH + col]);
            v.w = packh2(W1[(k0 + 24 + 2 * q) * NH + col], W1[(k0 + 25 + 2 * q) * NH + col]);
            ((uint4*)d_W1frag)[(b * 2 + h) * 32 + lane] = v;
        }
    } else if (b < 32) {
        int w = tid >> 5, l = tid & 31;
        int rbase = (b - 16) * 8 + w * 2;
#pragma unroll
        for (int rr = 0; rr < 2; rr++) {
            int h = rbase + rr;
            float s = W2[h * NH + l] * kw[l] + W2[h * NH + l + 32] * kw[l + 32] +
                      W2[h * NH + l + 64] * kw[l + 64] + W2[h * NH + l + 96] * kw[l + 96];
            for (int o = 16; o; o >>= 1) s += __shfl_xor_sync(0xffffffffu, s, o);
            if (l == 0) d_w2k[h] = s;
        }
    } else if (b < 36) {
        int i = (b - 32) * 128 + tid;
        d_sums[i] = 0.f; d_sl[i] = 0.f; d_cntf[i] = 0.f;
    } else {
        float c = (tid < NH) ? b2[tid] * kw[tid] : 0.f;
        for (int o = 16; o; o >>= 1) c += __shfl_xor_sync(0xffffffffu, c, o);
        __shared__ float red[4];
        if ((tid & 31) == 0) red[tid >> 5] = c;
        __syncthreads();
        if (tid == 0) d_c2 = red[0] + red[1] + red[2] + red[3];
    }
}

// ================== launch 1: fp16 m16n8k16 MLP ==================
// 256 threads/CTA, 128 clauses/CTA, one m16 tile per warp.
// feat staged as half2 (stride 72 halves = 144B, conflict-free A frags);
// B fragments LDG.128 from d_W1frag (16 KB, L1-resident).
#define HST 72
#define OFF_FEAT 0
#define OFF_B1   (128 * HST * 2)
#define OFF_WK   (OFF_B1 + 512)
#define SMEM_MLP (OFF_WK + 512)

__global__ void __launch_bounds__(256, 5) k_mlp(const float* __restrict__ feat,
                                                const float* __restrict__ b1) {
    extern __shared__ char smem[];
    __half* featS = (__half*)(smem + OFF_FEAT);
    float*  b1s   = (float*)(smem + OFF_B1);
    float*  wks   = (float*)(smem + OFF_WK);

    int tid = threadIdx.x;
    int wid = tid >> 5, lane = tid & 31;
    int g = lane >> 2, q = lane & 3;
    int base = blockIdx.x * 128;

    // stage A tile as half2 (zero-fill OOB rows): 8 float4 -> 8 uint2 per thread
    for (int i = tid; i < 128 * 16; i += 256) {
        int row = i >> 4, f4 = i & 15;
        float4 v = make_float4(0.f, 0.f, 0.f, 0.f);
        int c = base + row;
        if (c < NC) v = *(const float4*)(feat + (size_t)c * NF + f4 * 4);
        uint2 hv;
        hv.x = packh2(v.x, v.y);
        hv.y = packh2(v.z, v.w);
        *(uint2*)(featS + row * HST + f4 * 4) = hv;
    }
    if (tid < NH) { b1s[tid] = b1[tid]; wks[tid] = d_w2k[tid]; }
    __syncthreads();

    // A fragments: 4 k-steps of 16
    uint32_t a[4][4];
    int r0 = wid * 16 + g;
#pragma unroll
    for (int kt = 0; kt < 4; kt++) {
        int kb = kt * 16;
        a[kt][0] = *(const uint32_t*)(featS + r0 * HST + kb + 2 * q);
        a[kt][1] = *(const uint32_t*)(featS + (r0 + 8) * HST + kb + 2 * q);
        a[kt][2] = *(const uint32_t*)(featS + r0 * HST + kb + 2 * q + 8);
        a[kt][3] = *(const uint32_t*)(featS + (r0 + 8) * HST + kb + 2 * q + 8);
    }

    const uint4* fragp = (const uint4*)d_W1frag + lane;
    float acc0 = 0.f, acc1 = 0.f;
#pragma unroll
    for (int nt = 0; nt < 16; nt++) {
        uint4 F0 = fragp[(nt * 2 + 0) * 32];
        uint4 F1 = fragp[(nt * 2 + 1) * 32];
        float c0[4] = {0.f, 0.f, 0.f, 0.f};
        mma_f16(c0, a[0], F0.x, F0.y);
        mma_f16(c0, a[1], F0.z, F0.w);
        mma_f16(c0, a[2], F1.x, F1.y);
        mma_f16(c0, a[3], F1.z, F1.w);
        int col0 = nt * 8 + 2 * q, col1 = col0 + 1;
        float bb0 = b1s[col0], bb1 = b1s[col1];
        float wk0 = wks[col0], wk1 = wks[col1];
        acc0 += fmaxf(c0[0] + bb0, 0.f) * wk0 + fmaxf(c0[1] + bb1, 0.f) * wk1;
        acc1 += fmaxf(c0[2] + bb0, 0.f) * wk0 + fmaxf(c0[3] + bb1, 0.f) * wk1;
    }

    float c2v = d_c2;
#pragma unroll
    for (int rh = 0; rh < 2; rh++) {
        float v = (rh == 0) ? acc0 : acc1;
        v += __shfl_xor_sync(0xffffffffu, v, 1);
        v += __shfl_xor_sync(0xffffffffu, v, 2);
        v += c2v;
        int c = base + wid * 16 + rh * 8 + g;
        if (c < NC && q == 0) d_logits[c] = v;
    }
}

// ---- launch 2: fused denominator + numerator + count (R7 config, proven) ----
#define CHUNK 2048
#define DTPB 256
__global__ void __launch_bounds__(DTPB) k_denom(const int* __restrict__ sel,
                                                const int* __restrict__ proof) {
    __shared__ float es[CHUNK];
    __shared__ float pvs[CHUNK];
    __shared__ float pcs[CHUNK];
    int tid = threadIdx.x;
    int w = tid >> 5, l = tid & 31;
    int base = blockIdx.x * CHUNK;
    float shift = d_logits[0];

    for (int i = tid; i < CHUNK; i += DTPB) {
        int n = base + i;
        float e = 0.f, pv = 0.f, pc = 0.f;
        if (n < NC) {
            float lg = d_logits[n];
            e = expf(lg - shift);
            if (proof[n]) { pv = lg; pc = 1.f; }
        }
        es[i] = e; pvs[i] = pv; pcs[i] = pc;
    }
    __syncthreads();

    bool fast = (base + CHUNK) <= NC;
    for (int si = 0; si < 8; si++) {
        int s = blockIdx.y * 64 + si * 8 + w;
        const int* mrow = sel + (size_t)s * NC + base;
        float ad = 0.f, an = 0.f, ac = 0.f;
        if (fast) {
            const int4* m4 = (const int4*)mrow;
#pragma unroll
            for (int j = 0; j < 16; j++) {
                int p = j * 32 + l;
                int4 m = m4[p];
                float4 e4 = *(const float4*)&es[p * 4];
                float4 v4 = *(const float4*)&pvs[p * 4];
                float4 q4 = *(const float4*)&pcs[p * 4];
                if (m.x) { ad += e4.x; an += v4.x; ac += q4.x; }
                if (m.y) { ad += e4.y; an += v4.y; ac += q4.y; }
                if (m.z) { ad += e4.z; an += v4.z; ac += q4.z; }
                if (m.w) { ad += e4.w; an += v4.w; ac += q4.w; }
            }
        } else {
            for (int j = 0; j < 16; j++) {
                int e0 = j * 128 + l * 4;
#pragma unroll
                for (int p = 0; p < 4; p++) {
                    int n = base + e0 + p;
                    if (n < NC && mrow[e0 + p]) {
                        ad += es[e0 + p]; an += pvs[e0 + p]; ac += pcs[e0 + p];
                    }
                }
            }
        }
        for (int o = 16; o; o >>= 1) {
            ad += __shfl_xor_sync(0xffffffffu, ad, o);
            an += __shfl_xor_sync(0xffffffffu, an, o);
            ac += __shfl_xor_sync(0xffffffffu, ac, o);
        }
        if (l == 0) {
            atomicAdd(&d_sums[s], ad);
            atomicAdd(&d_sl[s], an);
            atomicAdd(&d_cntf[s], ac);
        }
    }
}

// ---- launch 3: final loss ----
__global__ void k_final(float* out) {
    float shift = d_logits[0];
    int t = threadIdx.x;  // 512
    float v = (shift + logf(d_sums[t])) - d_sl[t] / d_cntf[t];
    for (int o = 16; o; o >>= 1) v += __shfl_xor_sync(0xffffffffu, v, o);
    __shared__ float red[16];
    if ((t & 31) == 0) red[t >> 5] = v;
    __syncthreads();
    if (t == 0) {
        float tot = 0.f;
#pragma unroll
        for (int w = 0; w < 16; w++) tot += red[w];
        out[0] = tot / (float)NS;
    }
}

extern "C" void kernel_launch(void* const* d_in, const int* in_sizes, int n_in,
                              void* d_out, int out_size) {
    const float* feat = (const float*)d_in[0];
    const float* W1   = (const float*)d_in[1];
    const float* b1   = (const float*)d_in[2];
    const float* W2   = (const float*)d_in[3];
    const float* b2   = (const float*)d_in[4];
    const float* kw   = (const float*)d_in[5];
    const int*   sel  = (const int*)d_in[6];
    const int*   proof= (const int*)d_in[7];
    float* out = (float*)d_out;

    static int smem_set = 0;
    if (!smem_set) {
        cudaFuncSetAttribute(k_mlp, cudaFuncAttributeMaxDynamicSharedMemorySize, SMEM_MLP);
        smem_set = 1;
    }

    k_prep<<<37, 128>>>(W1, W2, b2, kw);                   // 0
    k_mlp<<<(NC + 127) / 128, 256, SMEM_MLP>>>(feat, b1);  // 1
    dim3 dg((NC + CHUNK - 1) / CHUNK, NS / 64);
    k_denom<<<dg, DTPB>>>(sel, proof);                     // 2
    k_final<<<1, NS>>>(out);                               // 3
}

// round 14
// speedup vs baseline: 1.2145x; 1.0034x over previous
#include <cuda_runtime.h>
#include <cuda_fp16.h>
#include <math.h>
#include <stdint.h>

#define NC 200000
#define NF 64
#define NH 128
#define NS 512

// ---- scratch ----
__device__ float    d_logits[NC];
__device__ float    d_w2k[NH];
__device__ uint32_t d_W1frag[NF * NH / 2];  // W1 as f16x2, MMA-fragment order (16 KB)
__device__ float    d_c2;
__device__ float    d_sums[NS];
__device__ float    d_sl[NS];
__device__ float    d_cntf[NS];
__device__ unsigned d_ticket;

__device__ __forceinline__ uint32_t packh2(float a, float b) {
    __half2 h = __floats2half2_rn(a, b);
    return *(uint32_t*)&h;
}

__device__ __forceinline__ void mma_f16(float c[4], const uint32_t a[4],
                                        uint32_t b0, uint32_t b1) {
    asm volatile(
        "mma.sync.aligned.m16n8k16.row.col.f32.f16.f16.f32 "
        "{%0,%1,%2,%3}, {%4,%5,%6,%7}, {%8,%9}, {%0,%1,%2,%3};"
        : "+f"(c[0]), "+f"(c[1]), "+f"(c[2]), "+f"(c[3])
        : "r"(a[0]), "r"(a[1]), "r"(a[2]), "r"(a[3]), "r"(b0), "r"(b1));
}

// ---- launch 0: prep (W1 f16 frag pack, w2k fold, accum init, c2, ticket) ----
__global__ void k_prep(const float* __restrict__ W1, const float* __restrict__ W2,
                       const float* __restrict__ b2, const float* __restrict__ kw) {
    int b = blockIdx.x;
    int tid = threadIdx.x;  // 128
    if (b < 16) {
        if (tid < 64) {
            int h = tid >> 5, lane = tid & 31;
            int q = lane & 3, g = lane >> 2;
            int col = b * 8 + g;
            int k0 = 32 * h;
            uint4 v;
            v.x = packh2(W1[(k0 + 2 * q) * NH + col],      W1[(k0 + 2 * q + 1) * NH + col]);
            v.y = packh2(W1[(k0 + 2 * q + 8) * NH + col],  W1[(k0 + 2 * q + 9) * NH + col]);
            v.z = packh2(W1[(k0 + 16 + 2 * q) * NH + col], W1[(k0 + 17 + 2 * q) * NH + col]);
            v.w = packh2(W1[(k0 + 24 + 2 * q) * NH + col], W1[(k0 + 25 + 2 * q) * NH + col]);
            ((uint4*)d_W1frag)[(b * 2 + h) * 32 + lane] = v;
        }
    } else if (b < 32) {
        int w = tid >> 5, l = tid & 31;
        int rbase = (b - 16) * 8 + w * 2;
#pragma unroll
        for (int rr = 0; rr < 2; rr++) {
            int h = rbase + rr;
            float s = W2[h * NH + l] * kw[l] + W2[h * NH + l + 32] * kw[l + 32] +
                      W2[h * NH + l + 64] * kw[l + 64] + W2[h * NH + l + 96] * kw[l + 96];
            for (int o = 16; o; o >>= 1) s += __shfl_xor_sync(0xffffffffu, s, o);
            if (l == 0) d_w2k[h] = s;
        }
    } else if (b < 36) {
        int i = (b - 32) * 128 + tid;
        d_sums[i] = 0.f; d_sl[i] = 0.f; d_cntf[i] = 0.f;
    } else {
        float c = (tid < NH) ? b2[tid] * kw[tid] : 0.f;
        for (int o = 16; o; o >>= 1) c += __shfl_xor_sync(0xffffffffu, c, o);
        __shared__ float red[4];
        if ((tid & 31) == 0) red[tid >> 5] = c;
        __syncthreads();
        if (tid == 0) {
            d_c2 = red[0] + red[1] + red[2] + red[3];
            d_ticket = 0u;
        }
    }
}

// ================== launch 1: fp16 m16n8k16 MLP ==================
#define HST 72
#define OFF_FEAT 0
#define OFF_B1   (128 * HST * 2)
#define OFF_WK   (OFF_B1 + 512)
#define SMEM_MLP (OFF_WK + 512)

__global__ void __launch_bounds__(256, 5) k_mlp(const float* __restrict__ feat,
                                                const float* __restrict__ b1) {
    extern __shared__ char smem[];
    __half* featS = (__half*)(smem + OFF_FEAT);
    float*  b1s   = (float*)(smem + OFF_B1);
    float*  wks   = (float*)(smem + OFF_WK);

    int tid = threadIdx.x;
    int wid = tid >> 5, lane = tid & 31;
    int g = lane >> 2, q = lane & 3;
    int base = blockIdx.x * 128;

    for (int i = tid; i < 128 * 16; i += 256) {
        int row = i >> 4, f4 = i & 15;
        float4 v = make_float4(0.f, 0.f, 0.f, 0.f);
        int c = base + row;
        if (c < NC) v = *(const float4*)(feat + (size_t)c * NF + f4 * 4);
        uint2 hv;
        hv.x = packh2(v.x, v.y);
        hv.y = packh2(v.z, v.w);
        *(uint2*)(featS + row * HST + f4 * 4) = hv;
    }
    if (tid < NH) { b1s[tid] = b1[tid]; wks[tid] = d_w2k[tid]; }
    __syncthreads();

    uint32_t a[4][4];
    int r0 = wid * 16 + g;
#pragma unroll
    for (int kt = 0; kt < 4; kt++) {
        int kb = kt * 16;
        a[kt][0] = *(const uint32_t*)(featS + r0 * HST + kb + 2 * q);
        a[kt][1] = *(const uint32_t*)(featS + (r0 + 8) * HST + kb + 2 * q);
        a[kt][2] = *(const uint32_t*)(featS + r0 * HST + kb + 2 * q + 8);
        a[kt][3] = *(const uint32_t*)(featS + (r0 + 8) * HST + kb + 2 * q + 8);
    }

    const uint4* fragp = (const uint4*)d_W1frag + lane;
    float acc0 = 0.f, acc1 = 0.f;
#pragma unroll
    for (int nt = 0; nt < 16; nt++) {
        uint4 F0 = fragp[(nt * 2 + 0) * 32];
        uint4 F1 = fragp[(nt * 2 + 1) * 32];
        float c0[4] = {0.f, 0.f, 0.f, 0.f};
        mma_f16(c0, a[0], F0.x, F0.y);
        mma_f16(c0, a[1], F0.z, F0.w);
        mma_f16(c0, a[2], F1.x, F1.y);
        mma_f16(c0, a[3], F1.z, F1.w);
        int col0 = nt * 8 + 2 * q, col1 = col0 + 1;
        float bb0 = b1s[col0], bb1 = b1s[col1];
        float wk0 = wks[col0], wk1 = wks[col1];
        acc0 += fmaxf(c0[0] + bb0, 0.f) * wk0 + fmaxf(c0[1] + bb1, 0.f) * wk1;
        acc1 += fmaxf(c0[2] + bb0, 0.f) * wk0 + fmaxf(c0[3] + bb1, 0.f) * wk1;
    }

    float c2v = d_c2;
#pragma unroll
    for (int rh = 0; rh < 2; rh++) {
        float v = (rh == 0) ? acc0 : acc1;
        v += __shfl_xor_sync(0xffffffffu, v, 1);
        v += __shfl_xor_sync(0xffffffffu, v, 2);
        v += c2v;
        int c = base + wid * 16 + rh * 8 + g;
        if (c < NC && q == 0) d_logits[c] = v;
    }
}

// ---- launch 2: fused denom + numerator + count + (last block) final loss ----
#define CHUNK 2048
#define DTPB 256
#define NBLK ((NC + CHUNK - 1) / CHUNK * (NS / 64))
__global__ void __launch_bounds__(DTPB) k_denom(const int* __restrict__ sel,
                                                const int* __restrict__ proof,
                                                float* __restrict__ out) {
    __shared__ float es[CHUNK];
    __shared__ float pvs[CHUNK];
    __shared__ float pcs[CHUNK];
    __shared__ int lastflag;
    int tid = threadIdx.x;
    int w = tid >> 5, l = tid & 31;
    int base = blockIdx.x * CHUNK;
    float shift = d_logits[0];

    for (int i = tid; i < CHUNK; i += DTPB) {
        int n = base + i;
        float e = 0.f, pv = 0.f, pc = 0.f;
        if (n < NC) {
            float lg = d_logits[n];
            e = expf(lg - shift);
            if (proof[n]) { pv = lg; pc = 1.f; }
        }
        es[i] = e; pvs[i] = pv; pcs[i] = pc;
    }
    __syncthreads();

    bool fast = (base + CHUNK) <= NC;
    for (int si = 0; si < 8; si++) {
        int s = blockIdx.y * 64 + si * 8 + w;
        const int* mrow = sel + (size_t)s * NC + base;
        float ad = 0.f, an = 0.f, ac = 0.f;
        if (fast) {
            const int4* m4 = (const int4*)mrow;
#pragma unroll
            for (int j = 0; j < 16; j++) {
                int p = j * 32 + l;
                int4 m = m4[p];
                float4 e4 = *(const float4*)&es[p * 4];
                float4 v4 = *(const float4*)&pvs[p * 4];
                float4 q4 = *(const float4*)&pcs[p * 4];
                if (m.x) { ad += e4.x; an += v4.x; ac += q4.x; }
                if (m.y) { ad += e4.y; an += v4.y; ac += q4.y; }
                if (m.z) { ad += e4.z; an += v4.z; ac += q4.z; }
                if (m.w) { ad += e4.w; an += v4.w; ac += q4.w; }
            }
        } else {
            for (int j = 0; j < 16; j++) {
                int e0 = j * 128 + l * 4;
#pragma unroll
                for (int p = 0; p < 4; p++) {
                    int n = base + e0 + p;
                    if (n < NC && mrow[e0 + p]) {
                        ad += es[e0 + p]; an += pvs[e0 + p]; ac += pcs[e0 + p];
                    }
                }
            }
        }
        for (int o = 16; o; o >>= 1) {
            ad += __shfl_xor_sync(0xffffffffu, ad, o);
            an += __shfl_xor_sync(0xffffffffu, an, o);
            ac += __shfl_xor_sync(0xffffffffu, ac, o);
        }
        if (l == 0) {
            atomicAdd(&d_sums[s], ad);
            atomicAdd(&d_sl[s], an);
            atomicAdd(&d_cntf[s], ac);
        }
    }

    // ---- last-block-done: compute the final loss inline ----
    if (tid == 0) {
        __threadfence();
        unsigned t = atomicAdd(&d_ticket, 1u);
        lastflag = (t == NBLK - 1u);
    }
    __syncthreads();
    if (lastflag) {
        float v = 0.f;
#pragma unroll
        for (int r = 0; r < 2; r++) {
            int s = tid + r * 256;
            v += (shift + logf(d_sums[s])) - d_sl[s] / d_cntf[s];
        }
        for (int o = 16; o; o >>= 1) v += __shfl_xor_sync(0xffffffffu, v, o);
        __shared__ float red[8];
        if (l == 0) red[w] = v;
        __syncthreads();
        if (tid == 0) {
            float tot = 0.f;
#pragma unroll
            for (int wv = 0; wv < 8; wv++) tot += red[wv];
            out[0] = tot / (float)NS;
        }
    }
}

extern "C" void kernel_launch(void* const* d_in, const int* in_sizes, int n_in,
                              void* d_out, int out_size) {
    const float* feat = (const float*)d_in[0];
    const float* W1   = (const float*)d_in[1];
    const float* b1   = (const float*)d_in[2];
    const float* W2   = (const float*)d_in[3];
    const float* b2   = (const float*)d_in[4];
    const float* kw   = (const float*)d_in[5];
    const int*   sel  = (const int*)d_in[6];
    const int*   proof= (const int*)d_in[7];
    float* out = (float*)d_out;

    static int smem_set = 0;
    if (!smem_set) {
        cudaFuncSetAttribute(k_mlp, cudaFuncAttributeMaxDynamicSharedMemorySize, SMEM_MLP);
        smem_set = 1;
    }

    k_prep<<<37, 128>>>(W1, W2, b2, kw);                   // 0
    k_mlp<<<(NC + 127) / 128, 256, SMEM_MLP>>>(feat, b1);  // 1
    dim3 dg((NC + CHUNK - 1) / CHUNK, NS / 64);
    k_denom<<<dg, DTPB>>>(sel, proof, out);                // 2
}